// round 3
// baseline (speedup 1.0000x reference)
#include <cuda_runtime.h>
#include <cfloat>
#include <math.h>

#define HIDDEN 128
#define MAXG   4096
#define CHUNK  256
#define GPB    16

// Scratch (allocation is forbidden -> device globals)
__device__ float g_sums[MAXG * HIDDEN];
__device__ float g_maxs[MAXG * HIDDEN];
__device__ int   g_cnts[MAXG];
__device__ int   g_is64;

// ---------------------------------------------------------------------------
// Kernel 0: re-init scratch every launch (graph replays) + batch dtype probe
// ---------------------------------------------------------------------------
__global__ void init_kernel(const void* batch_raw, int n_nodes, int g_total) {
    int idx = blockIdx.x * blockDim.x + threadIdx.x;
    int stride = gridDim.x * blockDim.x;
    int total = g_total * HIDDEN;
    for (int i = idx; i < total; i += stride) {
        g_sums[i] = 0.0f;
        g_maxs[i] = -FLT_MAX;
    }
    for (int i = idx; i < g_total; i += stride) g_cnts[i] = 0;

    if (blockIdx.x == 0 && threadIdx.x == 0) {
        // Detect whether batch is int64 or int32. Read only int32 words within
        // the first n_nodes*4 bytes (valid for both dtypes). For int64 data
        // (values < 2^31, little-endian) every odd 32-bit word is 0; for int32
        // data in the middle of the (sorted) buffer values are ~G/2 != 0.
        const int* p = (const int*)batch_raw;
        int off = (n_nodes / 2) & ~1;
        int K = 2048;
        if (off + K > n_nodes) { off = 0; K = n_nodes; }
        int odd_nonzero = 0;
        for (int i = 1; i < K; i += 2) odd_nonzero |= (p[off + i] != 0);
        g_is64 = odd_nonzero ? 0 : 1;
    }
}

// ---------------------------------------------------------------------------
// Kernel 1: streaming segment reduce over sorted batch ids
//   thread t owns hidden dim t; block owns CHUNK consecutive nodes.
// ---------------------------------------------------------------------------
__device__ __forceinline__ void flush_run(int g, float s, float m, int c, int tid) {
    atomicAdd(&g_sums[g * HIDDEN + tid], s);
    float* addr = &g_maxs[g * HIDDEN + tid];
    int mi = __float_as_int(m);
    if (mi >= 0) atomicMax((int*)addr, mi);
    else         atomicMin((unsigned int*)addr, __float_as_uint(m));
    if (tid == 0) atomicAdd(&g_cnts[g], c);
}

__global__ void __launch_bounds__(128) seg_kernel(const float* __restrict__ x,
                                                  const void* __restrict__ batch,
                                                  int n) {
    __shared__ int sb[CHUNK];
    int start = blockIdx.x * CHUNK;
    int cnt = n - start;
    if (cnt > CHUNK) cnt = CHUNK;
    if (cnt <= 0) return;
    int tid = threadIdx.x;

    if (g_is64) {
        const long long* b = (const long long*)batch;
        for (int i = tid; i < cnt; i += 128) sb[i] = (int)b[start + i];
    } else {
        const int* b = (const int*)batch;
        for (int i = tid; i < cnt; i += 128) sb[i] = b[start + i];
    }
    __syncthreads();

    const float* xp = x + (size_t)start * HIDDEN + tid;

    int   gcur = sb[0];
    float s = 0.0f, m = -FLT_MAX;
    int   c = 0;

    int i = 0;
    for (; i + 8 <= cnt; i += 8) {
        float v[8];
#pragma unroll
        for (int u = 0; u < 8; u++)
            v[u] = __ldcs(xp + (size_t)(i + u) * HIDDEN);
#pragma unroll
        for (int u = 0; u < 8; u++) {
            int g = sb[i + u];
            if (g != gcur) {                 // block-uniform branch (rare)
                flush_run(gcur, s, m, c, tid);
                gcur = g; s = 0.0f; m = -FLT_MAX; c = 0;
            }
            s += v[u];
            m = fmaxf(m, v[u]);
            c++;
        }
    }
    for (; i < cnt; i++) {
        float v = __ldcs(xp + (size_t)i * HIDDEN);
        int g = sb[i];
        if (g != gcur) {
            flush_run(gcur, s, m, c, tid);
            gcur = g; s = 0.0f; m = -FLT_MAX; c = 0;
        }
        s += v;
        m = fmaxf(m, v);
        c++;
    }
    if (c > 0) flush_run(gcur, s, m, c, tid);
}

// ---------------------------------------------------------------------------
// Kernel 2: pooled = [mean|max|sum] -> GEMV(W)+b -> LayerNorm -> exact GELU
//   GPB graphs per block amortize the 192KB W read.
// ---------------------------------------------------------------------------
__global__ void __launch_bounds__(128) finish_kernel(const float* __restrict__ W,
                                                     const float* __restrict__ bias,
                                                     const float* __restrict__ gamma,
                                                     const float* __restrict__ beta,
                                                     float* __restrict__ out) {
    __shared__ __align__(16) float pooled[GPB][3 * HIDDEN];
    __shared__ float hsh[GPB][HIDDEN];
    int tid = threadIdx.x;
    int g0 = blockIdx.x * GPB;

    // Build pooled features in shared
    for (int idx = tid; idx < GPB * 3 * HIDDEN; idx += 128) {
        int gl = idx / (3 * HIDDEN);
        int k  = idx - gl * (3 * HIDDEN);
        int g  = g0 + gl;
        float cntf = (float)g_cnts[g];
        float val;
        if (k < HIDDEN) {
            val = g_sums[g * HIDDEN + k] / fmaxf(cntf, 1.0f);           // mean
        } else if (k < 2 * HIDDEN) {
            float mv = g_maxs[g * HIDDEN + (k - HIDDEN)];               // max
            val = (cntf > 0.0f) ? mv : 0.0f;
        } else {
            val = g_sums[g * HIDDEN + (k - 2 * HIDDEN)];                // sum
        }
        pooled[gl][k] = val;
    }
    __syncthreads();

    // Register-blocked GEMV: thread t computes h[g][t] for all GPB graphs
    float acc[GPB];
    float bv = bias[tid];
#pragma unroll
    for (int j = 0; j < GPB; j++) acc[j] = bv;

    for (int k = 0; k < 3 * HIDDEN; k += 4) {
        float w0 = W[(k + 0) * HIDDEN + tid];
        float w1 = W[(k + 1) * HIDDEN + tid];
        float w2 = W[(k + 2) * HIDDEN + tid];
        float w3 = W[(k + 3) * HIDDEN + tid];
#pragma unroll
        for (int j = 0; j < GPB; j++) {
            float4 p = *reinterpret_cast<const float4*>(&pooled[j][k]);
            float a = acc[j];
            a = fmaf(p.x, w0, a);
            a = fmaf(p.y, w1, a);
            a = fmaf(p.z, w2, a);
            a = fmaf(p.w, w3, a);
            acc[j] = a;
        }
    }

#pragma unroll
    for (int j = 0; j < GPB; j++) hsh[j][tid] = acc[j];
    __syncthreads();

    // LayerNorm + GELU: warp w handles graphs w, w+4, ...
    int warp = tid >> 5, lane = tid & 31;
    for (int j = warp; j < GPB; j += 4) {
        float vv[4];
#pragma unroll
        for (int q = 0; q < 4; q++) vv[q] = hsh[j][lane + 32 * q];
        float sum = vv[0] + vv[1] + vv[2] + vv[3];
        float sq  = vv[0]*vv[0] + vv[1]*vv[1] + vv[2]*vv[2] + vv[3]*vv[3];
#pragma unroll
        for (int o = 16; o; o >>= 1) {
            sum += __shfl_xor_sync(0xffffffffu, sum, o);
            sq  += __shfl_xor_sync(0xffffffffu, sq, o);
        }
        float mu   = sum * (1.0f / 128.0f);
        float var  = fmaxf(sq * (1.0f / 128.0f) - mu * mu, 0.0f);
        float rstd = rsqrtf(var + 1e-5f);
        int g = g0 + j;
#pragma unroll
        for (int q = 0; q < 4; q++) {
            int d = lane + 32 * q;
            float y = (vv[q] - mu) * rstd * gamma[d] + beta[d];
            out[g * HIDDEN + d] = 0.5f * y * (1.0f + erff(y * 0.70710678118654752f));
        }
    }
}

// ---------------------------------------------------------------------------
extern "C" void kernel_launch(void* const* d_in, const int* in_sizes, int n_in,
                              void* d_out, int out_size) {
    const float* x     = (const float*)d_in[0];
    const void*  batch = d_in[1];
    int n = in_sizes[0] / HIDDEN;

    // Find W by its unique size (num_graphs scalar may or may not be an input)
    int wi = 2;
    while (wi < n_in && in_sizes[wi] != 3 * HIDDEN * HIDDEN) wi++;
    const float* W     = (const float*)d_in[wi];
    const float* bias  = (const float*)d_in[wi + 1];
    const float* gamma = (const float*)d_in[wi + 2];
    const float* beta  = (const float*)d_in[wi + 3];

    float* out = (float*)d_out;
    int G = out_size / HIDDEN;   // 4096

    init_kernel<<<256, 256>>>(batch, n, G);

    int nb = (n + CHUNK - 1) / CHUNK;
    seg_kernel<<<nb, 128>>>(x, batch, n);

    finish_kernel<<<G / GPB, 128>>>(W, bias, gamma, beta, out);
}

// round 4
// speedup vs baseline: 1.2004x; 1.2004x over previous
#include <cuda_runtime.h>
#include <cfloat>
#include <math.h>

#define HIDDEN 128
#define MAXG   4096
#define CHUNK  256
#define GPB    16
#define NPAIR  (GPB / 2)

// Scratch (allocation is forbidden -> device globals)
__device__ __align__(16) float g_sums[MAXG * HIDDEN];
__device__ __align__(16) float g_maxs[MAXG * HIDDEN];
__device__ int   g_cnts[MAXG];
__device__ int   g_is64;

// ---------------------------------------------------------------------------
// Kernel 0: re-init scratch every launch (graph replays) + PARALLEL dtype probe
// ---------------------------------------------------------------------------
__global__ void init_kernel(const void* batch_raw, int n_nodes, int g_total) {
    int idx = blockIdx.x * blockDim.x + threadIdx.x;
    int stride = gridDim.x * blockDim.x;
    int total4 = (g_total * HIDDEN) / 4;
    float4* s4 = reinterpret_cast<float4*>(g_sums);
    float4* m4 = reinterpret_cast<float4*>(g_maxs);
    float4 zz = make_float4(0.f, 0.f, 0.f, 0.f);
    float4 mm = make_float4(-FLT_MAX, -FLT_MAX, -FLT_MAX, -FLT_MAX);
    for (int i = idx; i < total4; i += stride) {
        s4[i] = zz;
        m4[i] = mm;
    }
    for (int i = idx; i < g_total; i += stride) g_cnts[i] = 0;

    // Parallel dtype probe (block 0 only). For int64 data (values < 2^31,
    // little-endian) every odd 32-bit word is 0; for int32 data the sampled
    // mid-buffer window holds sorted ids ~G/2 != 0.
    if (blockIdx.x == 0) {
        __shared__ int flag;
        if (threadIdx.x == 0) flag = 0;
        __syncthreads();
        const int* p = (const int*)batch_raw;
        int off = (n_nodes / 2) & ~1;
        int K = 4096;
        if (off + K > n_nodes) { off = 0; K = n_nodes; }
        int local = 0;
        for (int i = 1 + 2 * threadIdx.x; i < K; i += 2 * blockDim.x)
            local |= (p[off + i] != 0);
        if (local) atomicOr(&flag, 1);
        __syncthreads();
        if (threadIdx.x == 0) g_is64 = flag ? 0 : 1;
    }
}

// ---------------------------------------------------------------------------
// Kernel 1: streaming segment reduce over sorted batch ids
//   thread t owns hidden dim t; block owns CHUNK consecutive nodes.
// ---------------------------------------------------------------------------
__device__ __forceinline__ void flush_run(int g, float s, float m, int c, int tid) {
    atomicAdd(&g_sums[g * HIDDEN + tid], s);
    float* addr = &g_maxs[g * HIDDEN + tid];
    int mi = __float_as_int(m);
    if (mi >= 0) atomicMax((int*)addr, mi);
    else         atomicMin((unsigned int*)addr, __float_as_uint(m));
    if (tid == 0) atomicAdd(&g_cnts[g], c);
}

__global__ void __launch_bounds__(128) seg_kernel(const float* __restrict__ x,
                                                  const void* __restrict__ batch,
                                                  int n) {
    __shared__ int sb[CHUNK];
    int start = blockIdx.x * CHUNK;
    int cnt = n - start;
    if (cnt > CHUNK) cnt = CHUNK;
    if (cnt <= 0) return;
    int tid = threadIdx.x;

    if (g_is64) {
        const long long* b = (const long long*)batch;
        for (int i = tid; i < cnt; i += 128) sb[i] = (int)b[start + i];
    } else {
        const int* b = (const int*)batch;
        for (int i = tid; i < cnt; i += 128) sb[i] = b[start + i];
    }
    __syncthreads();

    const float* xp = x + (size_t)start * HIDDEN + tid;

    int   gcur = sb[0];
    float s = 0.0f, m = -FLT_MAX;
    int   c = 0;

    int i = 0;
    for (; i + 16 <= cnt; i += 16) {
        float v[16];
#pragma unroll
        for (int u = 0; u < 16; u++)
            v[u] = __ldcs(xp + (size_t)(i + u) * HIDDEN);
#pragma unroll
        for (int u = 0; u < 16; u++) {
            int g = sb[i + u];
            if (g != gcur) {                 // block-uniform branch (rare)
                flush_run(gcur, s, m, c, tid);
                gcur = g; s = 0.0f; m = -FLT_MAX; c = 0;
            }
            s += v[u];
            m = fmaxf(m, v[u]);
            c++;
        }
    }
    for (; i < cnt; i++) {
        float v = __ldcs(xp + (size_t)i * HIDDEN);
        int g = sb[i];
        if (g != gcur) {
            flush_run(gcur, s, m, c, tid);
            gcur = g; s = 0.0f; m = -FLT_MAX; c = 0;
        }
        s += v;
        m = fmaxf(m, v);
        c++;
    }
    if (c > 0) flush_run(gcur, s, m, c, tid);
}

// ---------------------------------------------------------------------------
// Packed fp32x2 helpers (sm_10x FFMA2 — ptxas won't auto-fuse; PTX only)
// ---------------------------------------------------------------------------
__device__ __forceinline__ unsigned long long pack_dup(float v) {
    unsigned long long r;
    asm("mov.b64 %0, {%1, %1};" : "=l"(r) : "f"(v));
    return r;
}
__device__ __forceinline__ unsigned long long fma_f32x2(
    unsigned long long a, unsigned long long b, unsigned long long c) {
    unsigned long long d;
    asm("fma.rn.f32x2 %0, %1, %2, %3;" : "=l"(d) : "l"(a), "l"(b), "l"(c));
    return d;
}
__device__ __forceinline__ void unpack2(unsigned long long v, float& lo, float& hi) {
    asm("mov.b64 {%0, %1}, %2;" : "=f"(lo), "=f"(hi) : "l"(v));
}

// ---------------------------------------------------------------------------
// Kernel 2: pooled = [mean|max|sum] -> GEMV(W)+b (FFMA2) -> LayerNorm -> GELU
//   Pooled features stored graph-pair-interleaved so the packed GEMV operand
//   is a direct LDS (no per-iteration register packing).
// ---------------------------------------------------------------------------
__global__ void __launch_bounds__(128) finish_kernel(const float* __restrict__ W,
                                                     const float* __restrict__ bias,
                                                     const float* __restrict__ gamma,
                                                     const float* __restrict__ beta,
                                                     float* __restrict__ out) {
    // pooled2[pair][k] = {pooled[2*pair][k], pooled[2*pair+1][k]}
    __shared__ __align__(16) float2 pooled2[NPAIR][3 * HIDDEN];
    __shared__ float hsh[GPB][HIDDEN];
    int tid = threadIdx.x;
    int g0 = blockIdx.x * GPB;

    // Build pooled features in shared (pair-interleaved)
    for (int idx = tid; idx < GPB * 3 * HIDDEN; idx += 128) {
        int gl = idx / (3 * HIDDEN);
        int k  = idx - gl * (3 * HIDDEN);
        int g  = g0 + gl;
        float cntf = (float)g_cnts[g];
        float val;
        if (k < HIDDEN) {
            val = g_sums[g * HIDDEN + k] / fmaxf(cntf, 1.0f);           // mean
        } else if (k < 2 * HIDDEN) {
            float mv = g_maxs[g * HIDDEN + (k - HIDDEN)];               // max
            val = (cntf > 0.0f) ? mv : 0.0f;
        } else {
            val = g_sums[g * HIDDEN + (k - 2 * HIDDEN)];                // sum
        }
        ((float*)&pooled2[gl >> 1][k])[gl & 1] = val;
    }
    __syncthreads();

    // Packed GEMV: thread t computes h[g][t] for all GPB graphs (2 per acc)
    unsigned long long acc2[NPAIR];
    {
        unsigned long long bv2 = pack_dup(bias[tid]);
#pragma unroll
        for (int j = 0; j < NPAIR; j++) acc2[j] = bv2;
    }

#pragma unroll 4
    for (int k = 0; k < 3 * HIDDEN; k += 2) {
        unsigned long long w0 = pack_dup(__ldg(&W[(k + 0) * HIDDEN + tid]));
        unsigned long long w1 = pack_dup(__ldg(&W[(k + 1) * HIDDEN + tid]));
#pragma unroll
        for (int j = 0; j < NPAIR; j++) {
            // float4 covers k and k+1 for the graph pair
            float4 p = *reinterpret_cast<const float4*>(&pooled2[j][k]);
            unsigned long long p0, p1;
            asm("mov.b64 %0, {%1, %2};" : "=l"(p0) : "f"(p.x), "f"(p.y));
            asm("mov.b64 %0, {%1, %2};" : "=l"(p1) : "f"(p.z), "f"(p.w));
            acc2[j] = fma_f32x2(p0, w0, acc2[j]);
            acc2[j] = fma_f32x2(p1, w1, acc2[j]);
        }
    }

#pragma unroll
    for (int j = 0; j < NPAIR; j++) {
        float lo, hi;
        unpack2(acc2[j], lo, hi);
        hsh[2 * j][tid]     = lo;
        hsh[2 * j + 1][tid] = hi;
    }
    __syncthreads();

    // LayerNorm + GELU: warp w handles graphs w, w+4, ...
    int warp = tid >> 5, lane = tid & 31;
    for (int j = warp; j < GPB; j += 4) {
        float vv[4];
#pragma unroll
        for (int q = 0; q < 4; q++) vv[q] = hsh[j][lane + 32 * q];
        float sum = vv[0] + vv[1] + vv[2] + vv[3];
        float sq  = vv[0]*vv[0] + vv[1]*vv[1] + vv[2]*vv[2] + vv[3]*vv[3];
#pragma unroll
        for (int o = 16; o; o >>= 1) {
            sum += __shfl_xor_sync(0xffffffffu, sum, o);
            sq  += __shfl_xor_sync(0xffffffffu, sq, o);
        }
        float mu   = sum * (1.0f / 128.0f);
        float var  = fmaxf(sq * (1.0f / 128.0f) - mu * mu, 0.0f);
        float rstd = rsqrtf(var + 1e-5f);
        int g = g0 + j;
#pragma unroll
        for (int q = 0; q < 4; q++) {
            int d = lane + 32 * q;
            float y = (vv[q] - mu) * rstd * gamma[d] + beta[d];
            out[g * HIDDEN + d] = 0.5f * y * (1.0f + erff(y * 0.70710678118654752f));
        }
    }
}

// ---------------------------------------------------------------------------
extern "C" void kernel_launch(void* const* d_in, const int* in_sizes, int n_in,
                              void* d_out, int out_size) {
    const float* x     = (const float*)d_in[0];
    const void*  batch = d_in[1];
    int n = in_sizes[0] / HIDDEN;

    // Find W by its unique size (num_graphs scalar may or may not be an input)
    int wi = 2;
    while (wi < n_in && in_sizes[wi] != 3 * HIDDEN * HIDDEN) wi++;
    const float* W     = (const float*)d_in[wi];
    const float* bias  = (const float*)d_in[wi + 1];
    const float* gamma = (const float*)d_in[wi + 2];
    const float* beta  = (const float*)d_in[wi + 3];

    float* out = (float*)d_out;
    int G = out_size / HIDDEN;   // 4096

    init_kernel<<<512, 256>>>(batch, n, G);

    int nb = (n + CHUNK - 1) / CHUNK;
    seg_kernel<<<nb, 128>>>(x, batch, n);

    finish_kernel<<<G / GPB, 128>>>(W, bias, gamma, beta, out);
}

// round 5
// speedup vs baseline: 1.3079x; 1.0896x over previous
#include <cuda_runtime.h>
#include <cfloat>
#include <math.h>

#define HIDDEN 128
#define MAXG   4096
#define CHUNK  512
#define GPB    16
#define NPAIR  (GPB / 2)

// Scratch (allocation is forbidden -> device globals).
// Zero-initialized at module load; finish_kernel re-zeroes after consuming,
// so every graph replay starts from a clean state. Max uses a monotone
// unsigned encoding whose identity is 0.
__device__ __align__(16) float    g_sums[MAXG * HIDDEN];
__device__ __align__(16) unsigned g_umaxs[MAXG * HIDDEN];
__device__ int g_cnts[MAXG];

// Monotone float<->unsigned order-preserving encoding (identity = 0)
__device__ __forceinline__ unsigned enc_f(float f) {
    unsigned u = __float_as_uint(f);
    return u ^ ((unsigned)((int)u >> 31) | 0x80000000u);
}
__device__ __forceinline__ float dec_f(unsigned u) {
    unsigned b = (u & 0x80000000u) ? (u & 0x7FFFFFFFu) : ~u;
    return __uint_as_float(b);
}

// ---------------------------------------------------------------------------
// Kernel 1: streaming segment reduce over sorted batch ids.
//   lane (tid&31) owns cols 4*lane..4*lane+3 (one float4 = full 512B row per warp)
//   rgrp (tid>>5) owns rows i with i%4==rgrp within the block's CHUNK rows.
// ---------------------------------------------------------------------------
__device__ __forceinline__ void flush4(int g, float4 s, float4 m, int c,
                                       int lane) {
    float* sp = &g_sums[g * HIDDEN + lane * 4];
    atomicAdd(sp + 0, s.x);
    atomicAdd(sp + 1, s.y);
    atomicAdd(sp + 2, s.z);
    atomicAdd(sp + 3, s.w);
    unsigned* mp = &g_umaxs[g * HIDDEN + lane * 4];
    atomicMax(mp + 0, enc_f(m.x));
    atomicMax(mp + 1, enc_f(m.y));
    atomicMax(mp + 2, enc_f(m.z));
    atomicMax(mp + 3, enc_f(m.w));
    if (lane == 0) atomicAdd(&g_cnts[g], c);
}

__global__ void __launch_bounds__(128) seg_kernel(const float* __restrict__ x,
                                                  const void* __restrict__ batch,
                                                  int n) {
    __shared__ int sb[CHUNK];
    __shared__ int s_is64;
    int start = blockIdx.x * CHUNK;
    int cnt = n - start;
    if (cnt > CHUNK) cnt = CHUNK;
    if (cnt <= 0) return;
    int tid = threadIdx.x;

    // dtype probe: for int64 ids (<2^31, little-endian) odd 32-bit words are 0;
    // for int32 the sorted mid-buffer ids are ~G/2 != 0. Two words checked.
    if (tid == 0) {
        const int* p = (const int*)batch;
        int off = (n / 2) & ~1;
        if (off + 4 > n) off = 0;
        s_is64 = (p[off + 1] == 0 && p[off + 3] == 0) ? 1 : 0;
    }
    __syncthreads();

    if (s_is64) {
        const long long* b = (const long long*)batch;
        for (int i = tid; i < cnt; i += 128) sb[i] = (int)b[start + i];
    } else {
        const int* b = (const int*)batch;
        for (int i = tid; i < cnt; i += 128) sb[i] = b[start + i];
    }
    __syncthreads();

    int lane = tid & 31;
    int rgrp = tid >> 5;
    if (rgrp >= cnt) return;

    const float4* xq = reinterpret_cast<const float4*>(x) +
                       (size_t)start * 32 + lane;

    int    gcur = sb[rgrp];
    float4 s = make_float4(0.f, 0.f, 0.f, 0.f);
    float4 m = make_float4(-FLT_MAX, -FLT_MAX, -FLT_MAX, -FLT_MAX);
    int    c = 0;

    int i = rgrp;
    for (; i + 28 < cnt; i += 32) {
        float4 v[8];
#pragma unroll
        for (int u = 0; u < 8; u++)
            v[u] = __ldcs(xq + (size_t)(i + 4 * u) * 32);
#pragma unroll
        for (int u = 0; u < 8; u++) {
            int g = sb[i + 4 * u];
            if (g != gcur) {                 // rare (runs avg ~244 rows)
                flush4(gcur, s, m, c, lane);
                gcur = g;
                s = make_float4(0.f, 0.f, 0.f, 0.f);
                m = make_float4(-FLT_MAX, -FLT_MAX, -FLT_MAX, -FLT_MAX);
                c = 0;
            }
            s.x += v[u].x; s.y += v[u].y; s.z += v[u].z; s.w += v[u].w;
            m.x = fmaxf(m.x, v[u].x); m.y = fmaxf(m.y, v[u].y);
            m.z = fmaxf(m.z, v[u].z); m.w = fmaxf(m.w, v[u].w);
            c++;
        }
    }
    for (; i < cnt; i += 4) {
        float4 v = __ldcs(xq + (size_t)i * 32);
        int g = sb[i];
        if (g != gcur) {
            flush4(gcur, s, m, c, lane);
            gcur = g;
            s = make_float4(0.f, 0.f, 0.f, 0.f);
            m = make_float4(-FLT_MAX, -FLT_MAX, -FLT_MAX, -FLT_MAX);
            c = 0;
        }
        s.x += v.x; s.y += v.y; s.z += v.z; s.w += v.w;
        m.x = fmaxf(m.x, v.x); m.y = fmaxf(m.y, v.y);
        m.z = fmaxf(m.z, v.z); m.w = fmaxf(m.w, v.w);
        c++;
    }
    if (c > 0) flush4(gcur, s, m, c, lane);
}

// ---------------------------------------------------------------------------
// Packed fp32x2 helpers (sm_10x FFMA2 — ptxas won't auto-fuse; PTX only)
// ---------------------------------------------------------------------------
__device__ __forceinline__ unsigned long long pack_dup(float v) {
    unsigned long long r;
    asm("mov.b64 %0, {%1, %1};" : "=l"(r) : "f"(v));
    return r;
}
__device__ __forceinline__ unsigned long long fma_f32x2(
    unsigned long long a, unsigned long long b, unsigned long long c) {
    unsigned long long d;
    asm("fma.rn.f32x2 %0, %1, %2, %3;" : "=l"(d) : "l"(a), "l"(b), "l"(c));
    return d;
}
__device__ __forceinline__ void unpack2(unsigned long long v, float& lo, float& hi) {
    asm("mov.b64 {%0, %1}, %2;" : "=f"(lo), "=f"(hi) : "l"(v));
}

// ---------------------------------------------------------------------------
// Kernel 2: pooled = [mean|max|sum] -> GEMV(W)+b (FFMA2) -> LayerNorm -> GELU
//   Also resets this block's scratch slots to the zero identity for the next
//   graph replay.
// ---------------------------------------------------------------------------
__global__ void __launch_bounds__(128) finish_kernel(const float* __restrict__ W,
                                                     const float* __restrict__ bias,
                                                     const float* __restrict__ gamma,
                                                     const float* __restrict__ beta,
                                                     float* __restrict__ out) {
    // pooled2[pair][k] = {pooled[2*pair][k], pooled[2*pair+1][k]}
    __shared__ __align__(16) float2 pooled2[NPAIR][3 * HIDDEN];
    __shared__ float hsh[GPB][HIDDEN];
    int tid = threadIdx.x;
    int g0 = blockIdx.x * GPB;

    // Build pooled features (single read of sums) + reset scratch.
    for (int idx = tid; idx < GPB * HIDDEN; idx += 128) {
        int gl = idx >> 7;
        int k  = idx & 127;
        int g  = g0 + gl;
        float cntf = (float)g_cnts[g];
        float sv = g_sums[g * HIDDEN + k];
        unsigned mu_ = g_umaxs[g * HIDDEN + k];
        float mean = sv / fmaxf(cntf, 1.0f);
        float mx   = (cntf > 0.0f) ? dec_f(mu_) : 0.0f;
        int pr = gl >> 1, h = gl & 1;
        ((float*)&pooled2[pr][k])[h]              = mean;
        ((float*)&pooled2[pr][HIDDEN + k])[h]     = mx;
        ((float*)&pooled2[pr][2 * HIDDEN + k])[h] = sv;
        // reset (same thread, same index partition -> no hazard)
        g_sums[g * HIDDEN + k]  = 0.0f;
        g_umaxs[g * HIDDEN + k] = 0u;
    }
    if (tid < GPB) g_cnts[g0 + tid] = 0;
    __syncthreads();

    // Packed GEMV: thread t computes h[g][t] for all GPB graphs (2 per acc)
    unsigned long long acc2[NPAIR];
    {
        unsigned long long bv2 = pack_dup(bias[tid]);
#pragma unroll
        for (int j = 0; j < NPAIR; j++) acc2[j] = bv2;
    }

#pragma unroll 4
    for (int k = 0; k < 3 * HIDDEN; k += 2) {
        unsigned long long w0 = pack_dup(__ldg(&W[(k + 0) * HIDDEN + tid]));
        unsigned long long w1 = pack_dup(__ldg(&W[(k + 1) * HIDDEN + tid]));
#pragma unroll
        for (int j = 0; j < NPAIR; j++) {
            float4 p = *reinterpret_cast<const float4*>(&pooled2[j][k]);
            unsigned long long p0, p1;
            asm("mov.b64 %0, {%1, %2};" : "=l"(p0) : "f"(p.x), "f"(p.y));
            asm("mov.b64 %0, {%1, %2};" : "=l"(p1) : "f"(p.z), "f"(p.w));
            acc2[j] = fma_f32x2(p0, w0, acc2[j]);
            acc2[j] = fma_f32x2(p1, w1, acc2[j]);
        }
    }

#pragma unroll
    for (int j = 0; j < NPAIR; j++) {
        float lo, hi;
        unpack2(acc2[j], lo, hi);
        hsh[2 * j][tid]     = lo;
        hsh[2 * j + 1][tid] = hi;
    }
    __syncthreads();

    // LayerNorm + GELU: warp w handles graphs w, w+4, ...
    int warp = tid >> 5, lane = tid & 31;
    for (int j = warp; j < GPB; j += 4) {
        float vv[4];
#pragma unroll
        for (int q = 0; q < 4; q++) vv[q] = hsh[j][lane + 32 * q];
        float sum = vv[0] + vv[1] + vv[2] + vv[3];
        float sq  = vv[0]*vv[0] + vv[1]*vv[1] + vv[2]*vv[2] + vv[3]*vv[3];
#pragma unroll
        for (int o = 16; o; o >>= 1) {
            sum += __shfl_xor_sync(0xffffffffu, sum, o);
            sq  += __shfl_xor_sync(0xffffffffu, sq, o);
        }
        float mu   = sum * (1.0f / 128.0f);
        float var  = fmaxf(sq * (1.0f / 128.0f) - mu * mu, 0.0f);
        float rstd = rsqrtf(var + 1e-5f);
        int g = g0 + j;
#pragma unroll
        for (int q = 0; q < 4; q++) {
            int d = lane + 32 * q;
            float y = (vv[q] - mu) * rstd * gamma[d] + beta[d];
            out[g * HIDDEN + d] = 0.5f * y * (1.0f + erff(y * 0.70710678118654752f));
        }
    }
}

// ---------------------------------------------------------------------------
extern "C" void kernel_launch(void* const* d_in, const int* in_sizes, int n_in,
                              void* d_out, int out_size) {
    const float* x     = (const float*)d_in[0];
    const void*  batch = d_in[1];
    int n = in_sizes[0] / HIDDEN;

    // Find W by its unique size (num_graphs scalar may or may not be an input)
    int wi = 2;
    while (wi < n_in && in_sizes[wi] != 3 * HIDDEN * HIDDEN) wi++;
    const float* W     = (const float*)d_in[wi];
    const float* bias  = (const float*)d_in[wi + 1];
    const float* gamma = (const float*)d_in[wi + 2];
    const float* beta  = (const float*)d_in[wi + 3];

    float* out = (float*)d_out;
    int G = out_size / HIDDEN;   // 4096

    int nb = (n + CHUNK - 1) / CHUNK;
    seg_kernel<<<nb, 128>>>(x, batch, n);

    finish_kernel<<<G / GPB, 128>>>(W, bias, gamma, beta, out);
}